// round 16
// baseline (speedup 1.0000x reference)
#include <cuda_runtime.h>
#include <cuda_fp16.h>

// Problem constants
#define NMAX   50000
#define EMAX   800000
#define IN_DIM 128
#define H1DIM  128   // HEADS*HID
#define NHEADS 4
#define HID    32
#define OUTD   64
#define SLOPE  0.2f

#define SCAN_CHUNK 1024
#define MAX_PARTS  64          // ceil(50000/1024)=49 < 64

// ---------------- scratch (static __device__ globals; no allocation) ----------
__device__ int    g_is64;
__device__ int    g_deg[NMAX];
__device__ int    g_off[NMAX];
__device__ int    g_cur[NMAX];
__device__ int    g_part[MAX_PARTS];      // -1 = not ready, >=0 = chunk aggregate
__device__ int    g_csr [EMAX];           // src per CSR slot
__device__ __half g_h1h[NMAX * H1DIM];    // layer-1 features, fp16 (gather payload)
__device__ float  g_als1[NMAX * NHEADS];
__device__ float  g_ald1[NMAX * NHEADS];
__device__ float  g_out1[NMAX * H1DIM];   // fp32 (GEMM2 input)
__device__ __half g_h2h[NMAX * OUTD];     // layer-2 features, fp16
__device__ float  g_als2[NMAX];
__device__ float  g_ald2[NMAX];

// ---------------- init: zero deg, init part flags, detect edge dtype ---------
// int64 edges (values < 2^31, little endian) -> every odd 32-bit word is 0.
__global__ void k_init(const unsigned int* __restrict__ ei32, int n) {
    int i = blockIdx.x * blockDim.x + threadIdx.x;
    if (i < n) g_deg[i] = 0;
    if (i < MAX_PARTS) g_part[i] = -1;
    if (blockIdx.x == 0 && threadIdx.x < 32) {
        unsigned v = ei32[threadIdx.x * 2 + 1];
        unsigned all0 = __all_sync(0xffffffffu, v == 0u);
        if (threadIdx.x == 0) g_is64 = (int)all0;
    }
}

__device__ __forceinline__ int edge_at(const void* p, long long i) {
    if (g_is64) return (int)((const long long*)p)[i];
    return ((const int*)p)[i];
}

// ---------------- CSR build --------------------------------------------------
__global__ void k_count(const void* __restrict__ ei, int e) {
    int i = blockIdx.x * blockDim.x + threadIdx.x;
    if (i < e) {
        int d = edge_at(ei, (long long)e + i);   // dst row
        atomicAdd(&g_deg[d], 1);
    }
}

// single-pass scan with decoupled lookback: grid = nb (<=49, all co-resident)
__global__ void k_scan(int n) {
    __shared__ int sm[256];
    __shared__ int prefix_sh;
    int b = blockIdx.x, t = threadIdx.x;
    int base = b * SCAN_CHUNK + t * 4;
    int v[4];
    int s = 0;
#pragma unroll
    for (int j = 0; j < 4; j++) {
        int i = base + j;
        v[j] = (i < n) ? g_deg[i] : 0;
        s += v[j];
    }
    sm[t] = s;
    __syncthreads();
#pragma unroll
    for (int d = 1; d < 256; d <<= 1) {
        int x = (t >= d) ? sm[t - d] : 0;
        __syncthreads();
        sm[t] += x;
        __syncthreads();
    }
    // publish this block's aggregate (value IS the payload; -1 means not ready)
    if (t == 0) atomicExch(&g_part[b], sm[255]);
    // warp 0: lookback over previous aggregates
    if (t < 32) {
        int lane = t;
        int pre = 0;
#pragma unroll
        for (int bb = 0; bb < MAX_PARTS; bb += 32) {
            int j = bb + lane;
            int val = 0;
            if (j < b) {
                do { val = atomicAdd(&g_part[j], 0); } while (val < 0);
            }
#pragma unroll
            for (int o = 16; o > 0; o >>= 1)
                val += __shfl_down_sync(0xffffffffu, val, o);
            if (lane == 0) pre += val;
        }
        if (lane == 0) prefix_sh = pre;
    }
    __syncthreads();
    int run = prefix_sh + ((t > 0) ? sm[t - 1] : 0);
#pragma unroll
    for (int j = 0; j < 4; j++) {
        int i = base + j;
        if (i < n) {
            g_off[i] = run;
            g_cur[i] = run;
            run += v[j];
        }
    }
}

__global__ void k_scatter(const void* __restrict__ ei, int e) {
    int i = blockIdx.x * blockDim.x + threadIdx.x;
    if (i < e) {
        int s = edge_at(ei, i);
        int d = edge_at(ei, (long long)e + i);
        int pos = atomicAdd(&g_cur[d], 1);
        g_csr[pos] = s;
    }
}

// ---------------- fp32 tiled GEMM, K = 128 fixed, fused alpha epilogue -------
// C (fp16)[M,BN] = A[M,128] @ B[128,BN]; als/ald fused from fp32 accumulators.
// 256 threads, BM=64, BK=32. Row r held by TX consecutive lanes.
template <int BN, int H>
__device__ __forceinline__ void gemm128(const float* __restrict__ A,
                                        const float* __restrict__ B,
                                        __half* __restrict__ C,
                                        const float* __restrict__ a_s,
                                        const float* __restrict__ a_d,
                                        float* __restrict__ als,
                                        float* __restrict__ ald, int M) {
    constexpr int K = 128, BM = 64, BK = 32;
    constexpr int TX = BN / 4;       // 32 (BN=128) or 16 (BN=64)
    constexpr int TY = 256 / TX;     // 8 or 16
    constexpr int TM = BM / TY;      // 8 or 4
    constexpr int RL = TX / H;       // lanes reduced per head: 8 (L1) / 16 (L2)
    __shared__ float As[BM][BK];
    __shared__ float Bs[BK][BN];
    int tid = threadIdx.x;
    int tx = tid % TX, ty = tid / TX;
    int row0 = blockIdx.x * BM;

    float acc[TM][4];
#pragma unroll
    for (int i = 0; i < TM; i++) { acc[i][0] = acc[i][1] = acc[i][2] = acc[i][3] = 0.f; }

    for (int kt = 0; kt < K; kt += BK) {
#pragma unroll
        for (int j = 0; j < (BM * BK) / 256; j++) {
            int idx = tid + j * 256;
            int r = idx >> 5;
            int kk = idx & 31;
            int grow = row0 + r;
            As[r][kk] = (grow < M) ? A[(long long)grow * K + kt + kk] : 0.f;
        }
#pragma unroll
        for (int j = 0; j < (BK * BN) / 256; j++) {
            int idx = tid + j * 256;
            int kk = idx / BN;
            int nn = idx % BN;
            Bs[kk][nn] = B[(kt + kk) * BN + nn];
        }
        __syncthreads();
#pragma unroll
        for (int kk = 0; kk < BK; kk++) {
            float4 b4 = *(const float4*)&Bs[kk][tx * 4];
#pragma unroll
            for (int i = 0; i < TM; i++) {
                float a = As[ty + i * TY][kk];
                acc[i][0] = fmaf(a, b4.x, acc[i][0]);
                acc[i][1] = fmaf(a, b4.y, acc[i][1]);
                acc[i][2] = fmaf(a, b4.z, acc[i][2]);
                acc[i][3] = fmaf(a, b4.w, acc[i][3]);
            }
        }
        __syncthreads();
    }

    // epilogue: fp16 store of C + fused alpha dot products (fp32)
    float4 s4 = *(const float4*)&a_s[tx * 4];
    float4 d4 = *(const float4*)&a_d[tx * 4];
#pragma unroll
    for (int i = 0; i < TM; i++) {
        int r = row0 + ty + i * TY;
        if (r < M) {
            float4 o = make_float4(acc[i][0], acc[i][1], acc[i][2], acc[i][3]);
            union { __half2 h2[2]; uint2 u; } cv;
            cv.h2[0] = __floats2half2_rn(o.x, o.y);
            cv.h2[1] = __floats2half2_rn(o.z, o.w);
            *(uint2*)&C[(long long)r * BN + tx * 4] = cv.u;
            float ps = o.x * s4.x + o.y * s4.y + o.z * s4.z + o.w * s4.w;
            float pd = o.x * d4.x + o.y * d4.y + o.z * d4.z + o.w * d4.w;
#pragma unroll
            for (int off = RL / 2; off > 0; off >>= 1) {
                ps += __shfl_xor_sync(0xffffffffu, ps, off);
                pd += __shfl_xor_sync(0xffffffffu, pd, off);
            }
            if ((tx % RL) == 0) {
                int head = tx / RL;
                als[r * H + head] = ps;
                ald[r * H + head] = pd;
            }
        }
    }
}

__global__ void k_gemm1(const float* __restrict__ x, const float* __restrict__ W1,
                        const float* __restrict__ a_s, const float* __restrict__ a_d, int M) {
    gemm128<H1DIM, NHEADS>(x, W1, g_h1h, a_s, a_d, g_als1, g_ald1, M);
}
__global__ void k_gemm2(const float* __restrict__ W2,
                        const float* __restrict__ a_s, const float* __restrict__ a_d, int M) {
    gemm128<OUTD, 1>(g_out1, W2, g_h2h, a_s, a_d, g_als2, g_ald2, M);
}

__device__ __forceinline__ float lrelu(float e) { return e > 0.f ? e : SLOPE * e; }

// ---------------- layer 1 aggregation: warp per dst, lane = channel ----------
__global__ void k_agg1(const float* __restrict__ b1, int n) {
    int w = (blockIdx.x * blockDim.x + threadIdx.x) >> 5;
    int lane = threadIdx.x & 31;
    if (w >= n) return;

    float4 ad4 = *(const float4*)&g_ald1[w * 4];
    float4 as4 = *(const float4*)&g_als1[w * 4];
    float adh[4] = {ad4.x, ad4.y, ad4.z, ad4.w};

    float acc[4], z[4];
    // self loop
    {
        const __half* hr = &g_h1h[(long long)w * 128 + lane];
        float wt0 = __expf(lrelu(as4.x + adh[0]));
        float wt1 = __expf(lrelu(as4.y + adh[1]));
        float wt2 = __expf(lrelu(as4.z + adh[2]));
        float wt3 = __expf(lrelu(as4.w + adh[3]));
        z[0] = wt0; z[1] = wt1; z[2] = wt2; z[3] = wt3;
        acc[0] = wt0 * __half2float(hr[0]);
        acc[1] = wt1 * __half2float(hr[32]);
        acc[2] = wt2 * __half2float(hr[64]);
        acc[3] = wt3 * __half2float(hr[96]);
    }

    int p = g_off[w];
    int end = p + g_deg[w];
    int s = (p < end) ? g_csr[p] : 0;
    for (; p < end; p++) {
        int sc = s;
        if (p + 1 < end) s = g_csr[p + 1];           // prefetch next src id
        float4 a2 = *(const float4*)&g_als1[sc * 4];
        const __half* hr = &g_h1h[(long long)sc * 128 + lane];
        float wt0 = __expf(lrelu(a2.x + adh[0]));
        float wt1 = __expf(lrelu(a2.y + adh[1]));
        float wt2 = __expf(lrelu(a2.z + adh[2]));
        float wt3 = __expf(lrelu(a2.w + adh[3]));
        z[0] += wt0; z[1] += wt1; z[2] += wt2; z[3] += wt3;
        acc[0] = fmaf(wt0, __half2float(hr[0]),  acc[0]);
        acc[1] = fmaf(wt1, __half2float(hr[32]), acc[1]);
        acc[2] = fmaf(wt2, __half2float(hr[64]), acc[2]);
        acc[3] = fmaf(wt3, __half2float(hr[96]), acc[3]);
    }
#pragma unroll
    for (int h = 0; h < 4; h++) {
        float v = acc[h] / (z[h] + 1e-16f) + b1[h * 32 + lane];
        g_out1[(long long)w * 128 + h * 32 + lane] = v > 0.f ? v : 0.f;
    }
}

// ---------------- layer 2 aggregation: warp per dst, lane covers c, c+32 -----
__global__ void k_agg2(const float* __restrict__ b2, float* __restrict__ out, int n) {
    int w = (blockIdx.x * blockDim.x + threadIdx.x) >> 5;
    int lane = threadIdx.x & 31;
    if (w >= n) return;

    float ad = g_ald2[w];
    float wt = __expf(lrelu(g_als2[w] + ad));        // self loop
    float z = wt;
    float acc0 = wt * __half2float(g_h2h[(long long)w * 64 + lane]);
    float acc1 = wt * __half2float(g_h2h[(long long)w * 64 + 32 + lane]);

    int p = g_off[w];
    int end = p + g_deg[w];
    int s = (p < end) ? g_csr[p] : 0;
    for (; p < end; p++) {
        int sc = s;
        if (p + 1 < end) s = g_csr[p + 1];
        float wt2 = __expf(lrelu(g_als2[sc] + ad));
        const __half* hr = &g_h2h[(long long)sc * 64 + lane];
        z += wt2;
        acc0 = fmaf(wt2, __half2float(hr[0]),  acc0);
        acc1 = fmaf(wt2, __half2float(hr[32]), acc1);
    }
    float inv = 1.f / (z + 1e-16f);
    out[(long long)w * 64 + lane]      = acc0 * inv + b2[lane];
    out[(long long)w * 64 + 32 + lane] = acc1 * inv + b2[32 + lane];
}

// ---------------- launch -----------------------------------------------------
extern "C" void kernel_launch(void* const* d_in, const int* in_sizes, int n_in,
                              void* d_out, int out_size) {
    const float* x   = (const float*)d_in[0];
    const void*  ei  = d_in[1];                    // edge_index [2,E], int64 or int32
    const float* W1  = (const float*)d_in[3];
    const float* as1 = (const float*)d_in[4];
    const float* ad1 = (const float*)d_in[5];
    const float* b1  = (const float*)d_in[6];
    const float* W2  = (const float*)d_in[7];
    const float* as2 = (const float*)d_in[8];
    const float* ad2 = (const float*)d_in[9];
    const float* b2  = (const float*)d_in[10];
    float* out = (float*)d_out;

    int n = in_sizes[0] / IN_DIM;                  // 50000
    int e = in_sizes[1] / 2;                       // 800000
    int nb = (n + SCAN_CHUNK - 1) / SCAN_CHUNK;    // 49

    // CSR build over dst (init -> count -> single-pass lookback scan -> scatter)
    k_init<<<(n + 255) / 256, 256>>>((const unsigned int*)ei, n);
    k_count<<<(e + 255) / 256, 256>>>(ei, e);
    k_scan<<<nb, 256>>>(n);
    k_scatter<<<(e + 255) / 256, 256>>>(ei, e);

    // layer 1
    k_gemm1<<<(n + 63) / 64, 256>>>(x, W1, as1, ad1, n);
    k_agg1<<<(n + 7) / 8, 256>>>(b1, n);

    // layer 2
    k_gemm2<<<(n + 63) / 64, 256>>>(W2, as2, ad2, n);
    k_agg2<<<(n + 7) / 8, 256>>>(b2, out, n);
}

// round 17
// speedup vs baseline: 1.2278x; 1.2278x over previous
#include <cuda_runtime.h>
#include <cuda_fp16.h>

// Problem constants
#define NMAX   50000
#define EMAX   800000
#define IN_DIM 128
#define H1DIM  128   // HEADS*HID
#define NHEADS 4
#define HID    32
#define OUTD   64
#define SLOPE  0.2f

#define SCAN_CHUNK 1024
#define MAX_PARTS  64          // ceil(50000/1024)=49 < 64

// ---------------- scratch (static __device__ globals; no allocation) ----------
__device__ int    g_is64;
__device__ int    g_deg[NMAX];
__device__ int    g_off[NMAX];
__device__ int    g_cur[NMAX];
__device__ int    g_part[MAX_PARTS];      // -1 = not ready, >=0 = chunk aggregate
__device__ int    g_csr [EMAX];           // src per CSR slot
__device__ __half g_h1h[NMAX * H1DIM];    // layer-1 features, fp16 (gather payload)
__device__ float  g_als1[NMAX * NHEADS];
__device__ float  g_ald1[NMAX * NHEADS];
__device__ float  g_out1[NMAX * H1DIM];   // fp32 (GEMM2 input)
__device__ __half g_h2h[NMAX * OUTD];     // layer-2 features, fp16
__device__ float  g_als2[NMAX];
__device__ float  g_ald2[NMAX];

// ---------------- packed f32x2 helpers (Blackwell FFMA2) ---------------------
__device__ __forceinline__ unsigned long long pk2(float x, float y) {
    unsigned long long r;
    asm("mov.b64 %0, {%1, %2};" : "=l"(r) : "f"(x), "f"(y));
    return r;
}
__device__ __forceinline__ unsigned long long ffma2(unsigned long long a,
                                                    unsigned long long b,
                                                    unsigned long long c) {
    unsigned long long d;
    asm("fma.rn.f32x2 %0, %1, %2, %3;" : "=l"(d) : "l"(a), "l"(b), "l"(c));
    return d;
}
__device__ __forceinline__ float2 upk2(unsigned long long v) {
    float2 f;
    asm("mov.b64 {%0, %1}, %2;" : "=f"(f.x), "=f"(f.y) : "l"(v));
    return f;
}

// ---------------- init: zero deg, init part flags, detect edge dtype ---------
// int64 edges (values < 2^31, little endian) -> every odd 32-bit word is 0.
__global__ void k_init(const unsigned int* __restrict__ ei32, int n) {
    int i = blockIdx.x * blockDim.x + threadIdx.x;
    if (i < n) g_deg[i] = 0;
    if (i < MAX_PARTS) g_part[i] = -1;
    if (blockIdx.x == 0 && threadIdx.x < 32) {
        unsigned v = ei32[threadIdx.x * 2 + 1];
        unsigned all0 = __all_sync(0xffffffffu, v == 0u);
        if (threadIdx.x == 0) g_is64 = (int)all0;
    }
}

__device__ __forceinline__ int edge_at(const void* p, long long i) {
    if (g_is64) return (int)((const long long*)p)[i];
    return ((const int*)p)[i];
}

// ---------------- CSR build --------------------------------------------------
__global__ void k_count(const void* __restrict__ ei, int e) {
    int i = blockIdx.x * blockDim.x + threadIdx.x;
    if (i < e) {
        int d = edge_at(ei, (long long)e + i);   // dst row
        atomicAdd(&g_deg[d], 1);
    }
}

// single-pass scan with decoupled lookback: grid = nb (<=49, all co-resident)
__global__ void k_scan(int n) {
    __shared__ int sm[256];
    __shared__ int prefix_sh;
    int b = blockIdx.x, t = threadIdx.x;
    int base = b * SCAN_CHUNK + t * 4;
    int v[4];
    int s = 0;
#pragma unroll
    for (int j = 0; j < 4; j++) {
        int i = base + j;
        v[j] = (i < n) ? g_deg[i] : 0;
        s += v[j];
    }
    sm[t] = s;
    __syncthreads();
#pragma unroll
    for (int d = 1; d < 256; d <<= 1) {
        int x = (t >= d) ? sm[t - d] : 0;
        __syncthreads();
        sm[t] += x;
        __syncthreads();
    }
    if (t == 0) atomicExch(&g_part[b], sm[255]);
    if (t < 32) {
        int lane = t;
        int pre = 0;
#pragma unroll
        for (int bb = 0; bb < MAX_PARTS; bb += 32) {
            int j = bb + lane;
            int val = 0;
            if (j < b) {
                do { val = atomicAdd(&g_part[j], 0); } while (val < 0);
            }
#pragma unroll
            for (int o = 16; o > 0; o >>= 1)
                val += __shfl_down_sync(0xffffffffu, val, o);
            if (lane == 0) pre += val;
        }
        if (lane == 0) prefix_sh = pre;
    }
    __syncthreads();
    int run = prefix_sh + ((t > 0) ? sm[t - 1] : 0);
#pragma unroll
    for (int j = 0; j < 4; j++) {
        int i = base + j;
        if (i < n) {
            g_off[i] = run;
            g_cur[i] = run;
            run += v[j];
        }
    }
}

__global__ void k_scatter(const void* __restrict__ ei, int e) {
    int i = blockIdx.x * blockDim.x + threadIdx.x;
    if (i < e) {
        int s = edge_at(ei, i);
        int d = edge_at(ei, (long long)e + i);
        int pos = atomicAdd(&g_cur[d], 1);
        g_csr[pos] = s;
    }
}

// ---------------- fp32x2 tiled GEMM, K = 128 fixed, fused alpha epilogue -----
// C (fp16)[M,BN] = A[M,128] @ B[128,BN]; als/ald fused from fp32 accumulators.
// 256 threads, BM=64, BK=32. Row r held by TX consecutive lanes.
template <int BN, int H>
__device__ __forceinline__ void gemm128(const float* __restrict__ A,
                                        const float* __restrict__ B,
                                        __half* __restrict__ C,
                                        const float* __restrict__ a_s,
                                        const float* __restrict__ a_d,
                                        float* __restrict__ als,
                                        float* __restrict__ ald, int M) {
    constexpr int K = 128, BM = 64, BK = 32;
    constexpr int TX = BN / 4;       // 32 (BN=128) or 16 (BN=64)
    constexpr int TY = 256 / TX;     // 8 or 16
    constexpr int TM = BM / TY;      // 8 or 4
    constexpr int RL = TX / H;       // lanes reduced per head: 8 (L1) / 16 (L2)
    __shared__ float As[BM][BK];
    __shared__ float Bs[BK][BN];
    int tid = threadIdx.x;
    int tx = tid % TX, ty = tid / TX;
    int row0 = blockIdx.x * BM;

    unsigned long long acc[TM][2];   // packed f32x2 accumulators
#pragma unroll
    for (int i = 0; i < TM; i++) { acc[i][0] = 0ull; acc[i][1] = 0ull; }

    for (int kt = 0; kt < K; kt += BK) {
#pragma unroll
        for (int j = 0; j < (BM * BK) / 256; j++) {
            int idx = tid + j * 256;
            int r = idx >> 5;
            int kk = idx & 31;
            int grow = row0 + r;
            As[r][kk] = (grow < M) ? A[(long long)grow * K + kt + kk] : 0.f;
        }
#pragma unroll
        for (int j = 0; j < (BK * BN) / 256; j++) {
            int idx = tid + j * 256;
            int kk = idx / BN;
            int nn = idx % BN;
            Bs[kk][nn] = B[(kt + kk) * BN + nn];
        }
        __syncthreads();
#pragma unroll
        for (int kk = 0; kk < BK; kk++) {
            float4 b4 = *(const float4*)&Bs[kk][tx * 4];
            unsigned long long bxy = pk2(b4.x, b4.y);
            unsigned long long bzw = pk2(b4.z, b4.w);
#pragma unroll
            for (int i = 0; i < TM; i++) {
                float a = As[ty + i * TY][kk];
                unsigned long long aa = pk2(a, a);
                acc[i][0] = ffma2(aa, bxy, acc[i][0]);
                acc[i][1] = ffma2(aa, bzw, acc[i][1]);
            }
        }
        __syncthreads();
    }

    // epilogue: fp16 store of C + fused alpha dot products (fp32)
    float4 s4 = *(const float4*)&a_s[tx * 4];
    float4 d4 = *(const float4*)&a_d[tx * 4];
#pragma unroll
    for (int i = 0; i < TM; i++) {
        int r = row0 + ty + i * TY;
        if (r < M) {
            float2 lo = upk2(acc[i][0]);
            float2 hi = upk2(acc[i][1]);
            float4 o = make_float4(lo.x, lo.y, hi.x, hi.y);
            union { __half2 h2[2]; uint2 u; } cv;
            cv.h2[0] = __floats2half2_rn(o.x, o.y);
            cv.h2[1] = __floats2half2_rn(o.z, o.w);
            *(uint2*)&C[(long long)r * BN + tx * 4] = cv.u;
            float ps = o.x * s4.x + o.y * s4.y + o.z * s4.z + o.w * s4.w;
            float pd = o.x * d4.x + o.y * d4.y + o.z * d4.z + o.w * d4.w;
#pragma unroll
            for (int off = RL / 2; off > 0; off >>= 1) {
                ps += __shfl_xor_sync(0xffffffffu, ps, off);
                pd += __shfl_xor_sync(0xffffffffu, pd, off);
            }
            if ((tx % RL) == 0) {
                int head = tx / RL;
                als[r * H + head] = ps;
                ald[r * H + head] = pd;
            }
        }
    }
}

__global__ void k_gemm1(const float* __restrict__ x, const float* __restrict__ W1,
                        const float* __restrict__ a_s, const float* __restrict__ a_d, int M) {
    gemm128<H1DIM, NHEADS>(x, W1, g_h1h, a_s, a_d, g_als1, g_ald1, M);
}
__global__ void k_gemm2(const float* __restrict__ W2,
                        const float* __restrict__ a_s, const float* __restrict__ a_d, int M) {
    gemm128<OUTD, 1>(g_out1, W2, g_h2h, a_s, a_d, g_als2, g_ald2, M);
}

__device__ __forceinline__ float lrelu(float e) { return e > 0.f ? e : SLOPE * e; }

// ---------------- layer 1 aggregation: warp per dst ---------------------------
// Lane l owns channels [4l, 4l+4): one LDG.64 per gathered row, one head
// (l/8) per lane -> one scalar als load + ONE __expf per edge per lane.
__global__ void k_agg1(const float* __restrict__ b1, int n) {
    int w = (blockIdx.x * blockDim.x + threadIdx.x) >> 5;
    int lane = threadIdx.x & 31;
    if (w >= n) return;

    int head = lane >> 3;                       // channels 4l..4l+3 all in head l/8
    float ad = g_ald1[w * 4 + head];

    float a0, a1, a2, a3, z;
    // self loop
    {
        float wt = __expf(lrelu(g_als1[w * 4 + head] + ad));
        uint2 raw = ((const uint2*)&g_h1h[(long long)w * 128])[lane];
        float2 f01 = __half22float2(*(__half2*)&raw.x);
        float2 f23 = __half22float2(*(__half2*)&raw.y);
        z = wt;
        a0 = wt * f01.x; a1 = wt * f01.y; a2 = wt * f23.x; a3 = wt * f23.y;
    }

    int p = g_off[w];
    int end = p + g_deg[w];
    int s = (p < end) ? g_csr[p] : 0;
    for (; p < end; p++) {
        int sc = s;
        if (p + 1 < end) s = g_csr[p + 1];      // prefetch next src id
        float wt = __expf(lrelu(g_als1[sc * 4 + head] + ad));
        uint2 raw = ((const uint2*)&g_h1h[(long long)sc * 128])[lane];
        float2 f01 = __half22float2(*(__half2*)&raw.x);
        float2 f23 = __half22float2(*(__half2*)&raw.y);
        z += wt;
        a0 = fmaf(wt, f01.x, a0);
        a1 = fmaf(wt, f01.y, a1);
        a2 = fmaf(wt, f23.x, a2);
        a3 = fmaf(wt, f23.y, a3);
    }
    float inv = 1.f / (z + 1e-16f);
    float4 bb = *(const float4*)&b1[lane * 4];
    float4 o;
    o.x = fmaf(a0, inv, bb.x); o.x = o.x > 0.f ? o.x : 0.f;
    o.y = fmaf(a1, inv, bb.y); o.y = o.y > 0.f ? o.y : 0.f;
    o.z = fmaf(a2, inv, bb.z); o.z = o.z > 0.f ? o.z : 0.f;
    o.w = fmaf(a3, inv, bb.w); o.w = o.w > 0.f ? o.w : 0.f;
    *(float4*)&g_out1[(long long)w * 128 + lane * 4] = o;
}

// ---------------- layer 2 aggregation: warp per dst ---------------------------
// Lane l owns channels {2l, 2l+1}: one LDG.32 (half2) per gathered row.
__global__ void k_agg2(const float* __restrict__ b2, float* __restrict__ out, int n) {
    int w = (blockIdx.x * blockDim.x + threadIdx.x) >> 5;
    int lane = threadIdx.x & 31;
    if (w >= n) return;

    float ad = g_ald2[w];
    float wt = __expf(lrelu(g_als2[w] + ad));        // self loop
    float z = wt;
    float2 fs = __half22float2(((const __half2*)&g_h2h[(long long)w * 64])[lane]);
    float acc0 = wt * fs.x;
    float acc1 = wt * fs.y;

    int p = g_off[w];
    int end = p + g_deg[w];
    int s = (p < end) ? g_csr[p] : 0;
    for (; p < end; p++) {
        int sc = s;
        if (p + 1 < end) s = g_csr[p + 1];
        float wt2 = __expf(lrelu(g_als2[sc] + ad));
        float2 f = __half22float2(((const __half2*)&g_h2h[(long long)sc * 64])[lane]);
        z += wt2;
        acc0 = fmaf(wt2, f.x, acc0);
        acc1 = fmaf(wt2, f.y, acc1);
    }
    float inv = 1.f / (z + 1e-16f);
    float2 o;
    o.x = fmaf(acc0, inv, b2[lane * 2]);
    o.y = fmaf(acc1, inv, b2[lane * 2 + 1]);
    *(float2*)&out[(long long)w * 64 + lane * 2] = o;
}

// ---------------- launch -----------------------------------------------------
extern "C" void kernel_launch(void* const* d_in, const int* in_sizes, int n_in,
                              void* d_out, int out_size) {
    const float* x   = (const float*)d_in[0];
    const void*  ei  = d_in[1];                    // edge_index [2,E], int64 or int32
    const float* W1  = (const float*)d_in[3];
    const float* as1 = (const float*)d_in[4];
    const float* ad1 = (const float*)d_in[5];
    const float* b1  = (const float*)d_in[6];
    const float* W2  = (const float*)d_in[7];
    const float* as2 = (const float*)d_in[8];
    const float* ad2 = (const float*)d_in[9];
    const float* b2  = (const float*)d_in[10];
    float* out = (float*)d_out;

    int n = in_sizes[0] / IN_DIM;                  // 50000
    int e = in_sizes[1] / 2;                       // 800000
    int nb = (n + SCAN_CHUNK - 1) / SCAN_CHUNK;    // 49

    // CSR build over dst (init -> count -> single-pass lookback scan -> scatter)
    k_init<<<(n + 255) / 256, 256>>>((const unsigned int*)ei, n);
    k_count<<<(e + 255) / 256, 256>>>(ei, e);
    k_scan<<<nb, 256>>>(n);
    k_scatter<<<(e + 255) / 256, 256>>>(ei, e);

    // layer 1
    k_gemm1<<<(n + 63) / 64, 256>>>(x, W1, as1, ad1, n);
    k_agg1<<<(n + 7) / 8, 256>>>(b1, n);

    // layer 2
    k_gemm2<<<(n + 63) / 64, 256>>>(W2, as2, ad2, n);
    k_agg2<<<(n + 7) / 8, 256>>>(b2, out, n);
}